// round 4
// baseline (speedup 1.0000x reference)
#include <cuda_runtime.h>
#include <math.h>

#define NB    4      // batch
#define S     363    // sinogram length / recon grid
#define A     180    // angles
#define W     256    // output size
#define CROP  53     // pad_before
#define RPADP 376    // padded pair-row stride (pairs); entries [364,376) stay .bss-zero

// pair[na][k] = (p[k-1], p[k]) with p[-1] = p[363] = 0  (p = filtered sinogram row)
__device__ float2 g_pairs[NB * A * RPADP];

// One block per (n, a) column. Spatial ramp-filter convolution, taps folded to
// immediates via full unroll:
// out[i] = 0.5*x[i] + sum_{d odd} (-2/(pi*d)^2) * (x[i-d] + x[i+d])
__global__ __launch_bounds__(384) void ramp_filter_kernel(const float* __restrict__ x) {
    const int na = blockIdx.x;
    const int n  = na / A;
    const int a  = na - n * A;

    __shared__ float xsp[S + 2 * 362];   // [0,362) zeros | [362,725) data | [725,1087) zeros

    const int t = threadIdx.x;
    if (t < 362) {
        xsp[t] = 0.0f;
        xsp[725 + t] = 0.0f;
    }
    // input layout: [n][1][s][a], a fastest
    for (int s = t; s < S; s += 384)
        xsp[362 + s] = x[(n * S + s) * A + a];
    __syncthreads();

    float* gr = (float*)(g_pairs + (size_t)na * RPADP);
    if (t < S) {
        const float* c = xsp + 362 + t;
        float acc = 0.5f * c[0];
        #pragma unroll
        for (int j = 0; j < 181; ++j) {
            const int d = 2 * j + 1;
            const float h = -2.0f / ((float)(M_PI * M_PI) * (float)d * (float)d);
            acc = fmaf(c[-d] + c[d], h, acc);
        }
        gr[2 * (t + 1)] = acc;   // pair[t+1].x = p[t]
        gr[2 * t + 1]   = acc;   // pair[t].y   = p[t]
    } else if (t == 363) {
        gr[0]           = 0.0f;  // pair[0].x   = p[-1]
        gr[2 * 363 + 1] = 0.0f;  // pair[363].y = p[363]
    }
}

// Tiled backprojection: one block = 16x16 output tile of one batch image.
// pos(xx,yy) = (xx-128)*cos - (yy-128)*sin + 181  (exact: 181*step == 1)
// Per angle the tile needs <= 23 consecutive pair entries -> staged in shared.
__global__ __launch_bounds__(128) void backproject_kernel(float* __restrict__ out) {
    const int n  = blockIdx.z;
    const int x0 = blockIdx.x * 16;
    const int y0 = blockIdx.y * 16;
    const int tid = threadIdx.x;

    __shared__ float4 tab[A];        // (cos, sin, 181 - st, -8*sin)
    __shared__ int    st1[A];        // first global pair index staged per angle
    __shared__ float2 sh2[A * 24];   // staged pairs, 24 per angle

    // Per-angle setup
    const float Ax0 = (float)(x0 - 128), Ax1 = Ax0 + 15.0f;
    const float By0 = (float)(y0 - 128), By1 = By0 + 15.0f;
    for (int a = tid; a < A; a += 128) {
        float sn, cs;
        sincosf((float)a * (float)(M_PI / 180.0), &sn, &cs);
        const float pmin = fminf(Ax0 * cs, Ax1 * cs)
                         + fminf(-By0 * sn, -By1 * sn) + 181.0f;
        const float st = floorf(pmin - 0.01f);   // guard for fp association diffs
        st1[a] = (int)st + 1;                    // global pair index of sh2[a][0]
        tab[a] = make_float4(cs, sn, 181.0f - st, -8.0f * sn);
    }
    __syncthreads();

    // Stage pairs: sh2[a*24 + j] = g_pairs[n][a][st1[a] + j]
    {
        const float2* __restrict__ gp = g_pairs + (size_t)n * (A * RPADP);
        #pragma unroll 4
        for (int idx = tid; idx < A * 24; idx += 128) {
            const int a  = idx / 24;
            const int jj = idx - a * 24;
            sh2[idx] = gp[a * RPADP + st1[a] + jj];
        }
    }
    __syncthreads();

    // Each thread: pixels (xx, yy) and (xx, yy+8)
    const int xx = x0 + (tid & 15);
    const int yy = y0 + (tid >> 4);
    const float xf = (float)(xx - 128);
    const float yf = (float)(yy - 128);

    float acc0a = 0.0f, accwa = 0.0f;
    float acc0b = 0.0f, accwb = 0.0f;

    const float2* shrow = sh2;
    #pragma unroll 4
    for (int a = 0; a < A; ++a, shrow += 24) {
        const float4 t4 = tab[a];
        const float q0 = fmaf(xf, t4.x, fmaf(-yf, t4.y, t4.z));  // pos - st, in (0, 23)
        const float q1 = q0 + t4.w;                              // pixel at yy+8
        const int j0 = (int)q0;                                  // trunc == floor (q > 0)
        const int j1 = (int)q1;
        const float w0 = q0 - (float)j0;
        const float w1 = q1 - (float)j1;
        const float2 v0 = shrow[j0];                             // (p[i-1], p[i]) LDS.64
        const float2 v1 = shrow[j1];
        acc0a += v0.x;
        accwa = fmaf(w0, v0.y - v0.x, accwa);
        acc0b += v1.x;
        accwb = fmaf(w1, v1.y - v1.x, accwb);
    }

    float* o = out + ((size_t)n * W + yy) * W + xx;
    o[0]         = (acc0a + accwa) * (float)(M_PI / 360.0);
    o[8 * W]     = (acc0b + accwb) * (float)(M_PI / 360.0);
}

extern "C" void kernel_launch(void* const* d_in, const int* in_sizes, int n_in,
                              void* d_out, int out_size) {
    const float* x = (const float*)d_in[0];
    float* out = (float*)d_out;

    ramp_filter_kernel<<<NB * A, 384>>>(x);
    backproject_kernel<<<dim3(16, 16, NB), 128>>>(out);
}

// round 5
// speedup vs baseline: 1.3529x; 1.3529x over previous
#include <cuda_runtime.h>
#include <math.h>

#define NB    4      // batch
#define S     363    // sinogram length / recon grid
#define A     180    // angles
#define W     256    // output size
#define CROP  53     // pad_before
#define RPADP 376    // padded pair-row stride; entries [364,376) stay .bss-zero

// pair[na][k] = (p[k-1], p[k]) with p[-1] = p[363] = 0  (p = filtered sinogram row)
__device__ float2 g_pairs[NB * A * RPADP];

// One block per (n, a) column. Spatial ramp-filter convolution, taps folded to
// immediates via full unroll:
// out[i] = 0.5*x[i] + sum_{d odd} (-2/(pi*d)^2) * (x[i-d] + x[i+d])
__global__ __launch_bounds__(384) void ramp_filter_kernel(const float* __restrict__ x) {
    const int na = blockIdx.x;
    const int n  = na / A;
    const int a  = na - n * A;

    __shared__ float xsp[S + 2 * 362];   // [0,362) zeros | [362,725) data | [725,1087) zeros

    const int t = threadIdx.x;
    if (t < 362) {
        xsp[t] = 0.0f;
        xsp[725 + t] = 0.0f;
    }
    // input layout: [n][1][s][a], a fastest
    for (int s = t; s < S; s += 384)
        xsp[362 + s] = x[(n * S + s) * A + a];
    __syncthreads();

    float* gr = (float*)(g_pairs + (size_t)na * RPADP);
    if (t < S) {
        const float* c = xsp + 362 + t;
        float acc = 0.5f * c[0];
        #pragma unroll
        for (int j = 0; j < 181; ++j) {
            const int d = 2 * j + 1;
            const float h = -2.0f / ((float)(M_PI * M_PI) * (float)d * (float)d);
            acc = fmaf(c[-d] + c[d], h, acc);
        }
        gr[2 * (t + 1)] = acc;   // pair[t+1].x = p[t]
        gr[2 * t + 1]   = acc;   // pair[t].y   = p[t]
    } else if (t == 363) {
        gr[0]           = 0.0f;  // pair[0].x   = p[-1]
        gr[2 * 363 + 1] = 0.0f;  // pair[363].y = p[363]
    }
}

#define CH  5                    // angles per pipeline chunk (180 = 36 chunks, even)
#define NCHUNK (A / CH)

// One block = one output row (256 px) of one batch image; 1 px/thread.
// Double-buffered software pipeline: issue chunk c+1's 5 gathers before
// consuming chunk c.
__global__ __launch_bounds__(256) void backproject_kernel(float* __restrict__ out) {
    const int n  = blockIdx.y;
    const int yy = blockIdx.x;
    const int xx = threadIdx.x;

    // per angle: (C = 181*cos, B = 181*(1 - uy*sin) + 1)
    __shared__ float2 scb[A];

    const float step = 2.0f / 362.0f;
    const float uy = fmaf((float)(yy + CROP), step, -1.0f);

    if (threadIdx.x < A) {
        float sn, cs;
        sincosf((float)threadIdx.x * (float)(M_PI / 180.0), &sn, &cs);
        scb[threadIdx.x] = make_float2(181.0f * cs, fmaf(-181.0f * uy, sn, 182.0f));
    }
    __syncthreads();

    const float ux = fmaf((float)(xx + CROP), step, -1.0f);
    const float2* __restrict__ base = g_pairs + (size_t)n * A * RPADP;

    float acc0 = 0.0f, accw = 0.0f;

    float2 va[CH], vb[CH];
    float  wa[CH], wb[CH];

    // load chunk c: indices + 5 independent LDG.64
    #define LOADC(c, vv, ww)                                             \
        {                                                                \
            const int a0 = (c) * CH;                                     \
            _Pragma("unroll")                                            \
            for (int k = 0; k < CH; ++k) {                               \
                const float2 cb = scb[a0 + k];                           \
                const float q = fmaf(ux, cb.x, cb.y);  /* in [0.98,363.02] */ \
                const int   i = (int)q;                /* trunc == floor */   \
                ww[k] = q - (float)i;                                    \
                vv[k] = __ldg(base + (a0 + k) * RPADP + i);              \
            }                                                            \
        }

    #define ACCC(vv, ww)                                                 \
        {                                                                \
            _Pragma("unroll")                                            \
            for (int k = 0; k < CH; ++k) {                               \
                acc0 += vv[k].x;                                         \
                accw = fmaf(ww[k], vv[k].y - vv[k].x, accw);             \
            }                                                            \
        }

    LOADC(0, va, wa)
    LOADC(1, vb, wb)
    #pragma unroll 1
    for (int c = 0; c + 2 < NCHUNK; c += 2) {
        ACCC(va, wa)
        LOADC(c + 2, va, wa)
        ACCC(vb, wb)
        LOADC(c + 3, vb, wb)
    }
    ACCC(va, wa)
    ACCC(vb, wb)

    #undef LOADC
    #undef ACCC

    out[((size_t)n * W + yy) * W + xx] = (acc0 + accw) * (float)(M_PI / 360.0);
}

extern "C" void kernel_launch(void* const* d_in, const int* in_sizes, int n_in,
                              void* d_out, int out_size) {
    const float* x = (const float*)d_in[0];
    float* out = (float*)d_out;

    ramp_filter_kernel<<<NB * A, 384>>>(x);
    backproject_kernel<<<dim3(W, NB), 256>>>(out);
}

// round 7
// speedup vs baseline: 1.5000x; 1.1087x over previous
#include <cuda_runtime.h>
#include <math.h>

#define NB    4      // batch
#define S     363    // sinogram length / recon grid
#define A     180    // angles
#define W     256    // output size
#define RP    364    // table row entries, k in [0,363]
#define NSTR  (A * RP)               // per-batch stride in float2

// tab[na][k] = (mid_k, delta_k), delta_k = p[k]-p[k-1], mid_k = p[k-1]+0.5*delta
// with p[-1] = p[363] = 0. Interp at q (=pos+1, floor k): p[k-1] + w*delta
// = mid + (w-0.5)*delta.
__device__ float2 g_tab[NB * NSTR];

// One block per (n, a) column. Spatial ramp-filter convolution, taps folded to
// immediates via full unroll:
// p[i] = 0.5*x[i] + sum_{d odd} (-2/(pi*d)^2) * (x[i-d] + x[i+d])
__global__ __launch_bounds__(384) void ramp_filter_kernel(const float* __restrict__ x) {
    const int na = blockIdx.x;
    const int n  = na / A;
    const int a  = na - n * A;

    __shared__ float xsp[S + 2 * 362];  // zeros | data | zeros
    __shared__ float ps[S + 2];         // p[-1..363], zero-padded ends

    const int t = threadIdx.x;
    if (t < 362) {
        xsp[t] = 0.0f;
        xsp[725 + t] = 0.0f;
    }
    if (t < 2) ps[t * 364] = 0.0f;      // ps[0] = p[-1] = 0, ps[364] = p[363] = 0
    // input layout: [n][1][s][a], a fastest
    for (int s = t; s < S; s += 384)
        xsp[362 + s] = x[(n * S + s) * A + a];
    __syncthreads();

    if (t < S) {
        const float* c = xsp + 362 + t;
        float acc = 0.5f * c[0];
        #pragma unroll
        for (int j = 0; j < 181; ++j) {
            const int d = 2 * j + 1;
            const float h = -2.0f / ((float)(M_PI * M_PI) * (float)d * (float)d);
            acc = fmaf(c[-d] + c[d], h, acc);
        }
        ps[t + 1] = acc;
    }
    __syncthreads();

    float2* gr = g_tab + (size_t)na * RP;
    if (t < RP) {                        // k = t in [0, 363]
        const float p0 = ps[t];          // p[k-1]
        const float p1 = ps[t + 1];      // p[k]
        const float d  = p1 - p0;
        gr[t] = make_float2(fmaf(0.5f, d, p0), d);
    }
}

#define CH 3                     // angles per pipeline chunk (180/3 = 60, even)
#define NCHUNK (A / CH)
#define MAGICF 12582912.0f       // 2^23 + 2^22
#define MAGICI 0x4B400000

// One block = one output row (256 px), all 4 batches fused per thread.
// q = xf*cos - yf*sin + 182 ; qp = q - 0.5 ; k = round(qp) via magic number,
// t = qp - k in [-0.5, 0.5]; value = mid[k] + t*delta[k].
__global__ __launch_bounds__(256) void backproject_kernel(float* __restrict__ out) {
    const int yy = blockIdx.x;
    const int xx = threadIdx.x;

    __shared__ float2 scb[A];    // (cos, 181.5 - yf*sin)

    const float yf = (float)(yy - 128);
    if (threadIdx.x < A) {
        float sn, cs;
        sincosf((float)threadIdx.x * (float)(M_PI / 180.0), &sn, &cs);
        scb[threadIdx.x] = make_float2(cs, fmaf(-yf, sn, 181.5f));
    }
    __syncthreads();

    const float xf = (float)(xx - 128);

    float accm0 = 0.f, accm1 = 0.f, accm2 = 0.f, accm3 = 0.f;
    float accd0 = 0.f, accd1 = 0.f, accd2 = 0.f, accd3 = 0.f;

    float2 va[CH * NB], vb[CH * NB];
    float  wa[CH], wb[CH];

    #define LOADC(c, vv, ww)                                                  \
        {                                                                     \
            const int a0 = (c) * CH;                                          \
            _Pragma("unroll")                                                 \
            for (int k = 0; k < CH; ++k) {                                    \
                const float2 cb = scb[a0 + k];                                \
                const float qp = fmaf(xf, cb.x, cb.y);   /* q - 0.5 */        \
                const float f  = qp + MAGICF;                                 \
                const float il = f - MAGICF;             /* round(qp) */      \
                ww[k] = qp - il;                         /* in [-.5,.5] */    \
                const int i = __float_as_int(f) - MAGICI;                     \
                const float2* p = g_tab + (a0 + k) * RP + i;                  \
                _Pragma("unroll")                                             \
                for (int n = 0; n < NB; ++n)                                  \
                    vv[k * NB + n] = __ldg(p + n * NSTR);                     \
            }                                                                 \
        }

    #define ACCC(vv, ww)                                                      \
        {                                                                     \
            _Pragma("unroll")                                                 \
            for (int k = 0; k < CH; ++k) {                                    \
                accm0 += vv[k * NB + 0].x;                                    \
                accd0 = fmaf(ww[k], vv[k * NB + 0].y, accd0);                 \
                accm1 += vv[k * NB + 1].x;                                    \
                accd1 = fmaf(ww[k], vv[k * NB + 1].y, accd1);                 \
                accm2 += vv[k * NB + 2].x;                                    \
                accd2 = fmaf(ww[k], vv[k * NB + 2].y, accd2);                 \
                accm3 += vv[k * NB + 3].x;                                    \
                accd3 = fmaf(ww[k], vv[k * NB + 3].y, accd3);                 \
            }                                                                 \
        }

    LOADC(0, va, wa)
    LOADC(1, vb, wb)
    #pragma unroll 1
    for (int c = 0; c + 2 < NCHUNK; c += 2) {
        ACCC(va, wa)
        LOADC(c + 2, va, wa)
        ACCC(vb, wb)
        LOADC(c + 3, vb, wb)
    }
    ACCC(va, wa)
    ACCC(vb, wb)

    #undef LOADC
    #undef ACCC

    const float sc = (float)(M_PI / 360.0);
    float* o = out + (size_t)yy * W + xx;
    o[0 * W * W] = (accm0 + accd0) * sc;
    o[1 * W * W] = (accm1 + accd1) * sc;
    o[2 * W * W] = (accm2 + accd2) * sc;
    o[3 * W * W] = (accm3 + accd3) * sc;
}

extern "C" void kernel_launch(void* const* d_in, const int* in_sizes, int n_in,
                              void* d_out, int out_size) {
    const float* x = (const float*)d_in[0];
    float* out = (float*)d_out;

    ramp_filter_kernel<<<NB * A, 384>>>(x);
    backproject_kernel<<<W, 256>>>(out);
}